// round 3
// baseline (speedup 1.0000x reference)
#include <cuda_runtime.h>
#include <cuda_fp16.h>

#define EPSV 1e-8f

constexpr int Bb = 64;
constexpr int N0 = 20000, E0 = 200000, M0 = 8000;
constexpr int E1 = 80000,  M1 = 2000;
constexpr int E2 = 20000,  M2 = 500;
constexpr int ETOT = E0 + E1 + E2;
constexpr int MTOT = M0 + M1 + M2;

constexpr int TB = 1250;                       // transpose blocks (625 x 2)
constexpr int EB = (ETOT / 4 + 255) / 256;     // edge blocks, 4 edges/thread

// ---- scratch (device globals; zero-initialized at module load) ----
__device__ __half g_xT[N0 * Bb];               // x transposed to (node, batch), fp16
__device__ int    g_cnt[MTOT];                 // per-dst degree counters (re-zeroed by k_scan)
__device__ int    g_slot[ETOT];                // per-edge slot within its dst bucket
__device__ int    g_rp0[M0 + 1], g_rp1[M1 + 1], g_rp2[M2 + 1];
__device__ int    g_ce0[E0], g_ce1[E1], g_ce2[E2];
__device__ __half g_d1[M0 * Bb * 8];           // layer-0 out, (node, batch, h), fp16
__device__ __half g_d2[M1 * Bb * 8];
__device__ float  g_d3[M2 * Bb * 8];           // final layer fp32

// ---- K1: transpose x (B,N0) -> (N0,B) fp16  ∥  histogram + slot assignment ----
__global__ void k_pre(const float* __restrict__ x,
                      const int* __restrict__ d0, const int* __restrict__ d1,
                      const int* __restrict__ d2) {
    if (blockIdx.x < TB) {
        __shared__ float tile[32][33];
        int bx = blockIdx.x % 625, by = blockIdx.x / 625;
        int tx = threadIdx.x & 31, ty = threadIdx.x >> 5;
        int nb = bx * 32, bb = by * 32;
#pragma unroll
        for (int i = 0; i < 32; i += 8)
            tile[ty + i][tx] = x[(bb + ty + i) * N0 + nb + tx];
        __syncthreads();
#pragma unroll
        for (int i = 0; i < 32; i += 8)
            g_xT[(nb + ty + i) * Bb + bb + tx] = __float2half_rn(tile[tx][ty + i]);
    } else {
        int i0 = ((blockIdx.x - TB) * 256 + threadIdx.x) * 4;
        if (i0 >= ETOT) return;
        const int* dp; int* cnt; int off;
        if (i0 < E0)            { dp = d0; cnt = g_cnt;            off = 0; }
        else if (i0 < E0 + E1)  { dp = d1; cnt = g_cnt + M0;       off = E0; }
        else                    { dp = d2; cnt = g_cnt + M0 + M1;  off = E0 + E1; }
        int4 dd = *(const int4*)&dp[i0 - off];
        int s0 = atomicAdd(&cnt[dd.x], 1);
        int s1 = atomicAdd(&cnt[dd.y], 1);
        int s2 = atomicAdd(&cnt[dd.z], 1);
        int s3 = atomicAdd(&cnt[dd.w], 1);
        *(int4*)&g_slot[i0] = make_int4(s0, s1, s2, s3);
    }
}

// ---- K2: exclusive scan (warp-shuffle, 8 elems/thread), then zero the counters ----
__global__ void k_scan() {
    const int L = blockIdx.x;
    int* cnt       = (L == 0) ? g_cnt  : (L == 1) ? g_cnt + M0 : g_cnt + M0 + M1;
    int* rp        = (L == 0) ? g_rp0  : (L == 1) ? g_rp1      : g_rp2;
    const int m    = (L == 0) ? M0     : (L == 1) ? M1         : M2;

    int t = threadIdx.x;
    int base = t * 8;
    int v[8];
    int s = 0;
#pragma unroll
    for (int k = 0; k < 8; k++) {
        int c = (base + k < m) ? cnt[base + k] : 0;
        s += c;
        v[k] = s;                       // inclusive prefix within thread
    }
    int lane = t & 31, wid = t >> 5;
    int inc = s;
#pragma unroll
    for (int off = 1; off < 32; off <<= 1) {
        int n = __shfl_up_sync(0xffffffffu, inc, off);
        if (lane >= off) inc += n;
    }
    int wexcl = inc - s;
    __shared__ int wtot[32];
    if (lane == 31) wtot[wid] = inc;
    __syncthreads();
    if (t < 32) {
        int w = wtot[t];
        int wi = w;
#pragma unroll
        for (int off = 1; off < 32; off <<= 1) {
            int n = __shfl_up_sync(0xffffffffu, wi, off);
            if (t >= off) wi += n;
        }
        wtot[t] = wi - w;
    }
    __syncthreads();
    int off0 = wtot[wid] + wexcl;
#pragma unroll
    for (int k = 0; k < 8; k++)
        if (base + k < m) { rp[base + k + 1] = off0 + v[k]; cnt[base + k] = 0; }
    if (t == 0) rp[0] = 0;
}

// ---- K3: fill CSR via precomputed slots (no atomics) ----
__global__ void k_fill(const int* __restrict__ s0, const int* __restrict__ d0,
                       const int* __restrict__ s1, const int* __restrict__ d1,
                       const int* __restrict__ s2, const int* __restrict__ d2) {
    int i0 = (blockIdx.x * 256 + threadIdx.x) * 4;
    if (i0 >= ETOT) return;
    const int *sp, *dp, *rp; int* ce; int off;
    if (i0 < E0)            { sp = s0; dp = d0; rp = g_rp0; ce = g_ce0; off = 0; }
    else if (i0 < E0 + E1)  { sp = s1; dp = d1; rp = g_rp1; ce = g_ce1; off = E0; }
    else                    { sp = s2; dp = d2; rp = g_rp2; ce = g_ce2; off = E0 + E1; }
    int j = i0 - off;
    int4 ss = *(const int4*)&sp[j];
    int4 dd = *(const int4*)&dp[j];
    int4 sl = *(const int4*)&g_slot[i0];
    ce[rp[dd.x] + sl.x] = ss.x;
    ce[rp[dd.y] + sl.y] = ss.y;
    ce[rp[dd.z] + sl.z] = ss.z;
    ce[rp[dd.w] + sl.w] = ss.w;
}

// ---- K4: layer 0 — scalar scatter-mean + analytic minmax through W0 + relu ----
__global__ void k_agg0(const float* __restrict__ W0) {
    int group = threadIdx.x >> 6;
    int b = threadIdx.x & 63;
    int node = blockIdx.x * 4 + group;
    int beg = g_rp0[node], end = g_rp0[node + 1];
    float s = 0.f;
    for (int j = beg; j < end; j++) {
        int src = g_ce0[j];
        s += __half2float(g_xT[src * Bb + b]);
    }
    s *= 1.f / fmaxf((float)(end - beg), 1.f);
    float mn = s, mx = s;
#pragma unroll
    for (int off = 16; off; off >>= 1) {
        mn = fminf(mn, __shfl_xor_sync(0xffffffffu, mn, off));
        mx = fmaxf(mx, __shfl_xor_sync(0xffffffffu, mx, off));
    }
    __shared__ float shmn[4][2], shmx[4][2];
    int wig = b >> 5;
    if ((b & 31) == 0) { shmn[group][wig] = mn; shmx[group][wig] = mx; }
    __syncthreads();
    mn = fminf(shmn[group][0], shmn[group][1]);
    mx = fmaxf(shmx[group][0], shmx[group][1]);
    __half2 out[4];
#pragma unroll
    for (int h = 0; h < 4; h++) {
        float w0 = W0[2 * h], w1 = W0[2 * h + 1];
        float lo0 = (w0 >= 0.f) ? w0 * mn : w0 * mx;
        float hi0 = (w0 >= 0.f) ? w0 * mx : w0 * mn;
        float lo1 = (w1 >= 0.f) ? w1 * mn : w1 * mx;
        float hi1 = (w1 >= 0.f) ? w1 * mx : w1 * mn;
        float r0 = fmaxf((w0 * s - lo0) / (hi0 - lo0 + EPSV), 0.f);
        float r1 = fmaxf((w1 * s - lo1) / (hi1 - lo1 + EPSV), 0.f);
        out[h] = __floats2half2_rn(r0, r1);
    }
    *(uint4*)&g_d1[(node * Bb + b) * 8] = *(uint4*)out;
}

// ---- K5/K6: layers 1/2 — vector scatter-mean, W after mean, minmax, relu ----
__global__ void k_aggL(const float* __restrict__ W, int L) {
    const int*    rp  = (L == 1) ? g_rp1 : g_rp2;
    const int*    ce  = (L == 1) ? g_ce1 : g_ce2;
    const __half* din = (L == 1) ? g_d1  : g_d2;
    int group = threadIdx.x >> 6;
    int b = threadIdx.x & 63;
    int node = blockIdx.x * 2 + group;
    __shared__ float sW[64];
    if (threadIdx.x < 64) sW[threadIdx.x] = W[threadIdx.x];
    __syncthreads();
    int beg = rp[node], end = rp[node + 1];
    float acc[8];
#pragma unroll
    for (int h = 0; h < 8; h++) acc[h] = 0.f;
    for (int j = beg; j < end; j++) {
        int src = ce[j];
        uint4 raw = *(const uint4*)&din[(src * Bb + b) * 8];
        float2 f0 = __half22float2(*(__half2*)&raw.x);
        float2 f1 = __half22float2(*(__half2*)&raw.y);
        float2 f2 = __half22float2(*(__half2*)&raw.z);
        float2 f3 = __half22float2(*(__half2*)&raw.w);
        acc[0] += f0.x; acc[1] += f0.y; acc[2] += f1.x; acc[3] += f1.y;
        acc[4] += f2.x; acc[5] += f2.y; acc[6] += f3.x; acc[7] += f3.y;
    }
    float inv = 1.f / fmaxf((float)(end - beg), 1.f);
    float t[8], mn[8], mx[8];
#pragma unroll
    for (int h = 0; h < 8; h++) {
        float v = 0.f;
#pragma unroll
        for (int d = 0; d < 8; d++) v += sW[h * 8 + d] * acc[d];
        t[h] = v * inv;
        mn[h] = t[h]; mx[h] = t[h];
    }
#pragma unroll
    for (int off = 16; off; off >>= 1) {
#pragma unroll
        for (int h = 0; h < 8; h++) {
            mn[h] = fminf(mn[h], __shfl_xor_sync(0xffffffffu, mn[h], off));
            mx[h] = fmaxf(mx[h], __shfl_xor_sync(0xffffffffu, mx[h], off));
        }
    }
    __shared__ float smn[2][2][8], smx[2][2][8];
    int wig = b >> 5;
    if ((b & 31) == 0) {
#pragma unroll
        for (int h = 0; h < 8; h++) { smn[group][wig][h] = mn[h]; smx[group][wig][h] = mx[h]; }
    }
    __syncthreads();
    float out[8];
#pragma unroll
    for (int h = 0; h < 8; h++) {
        float lo = fminf(smn[group][0][h], smn[group][1][h]);
        float hi = fmaxf(smx[group][0][h], smx[group][1][h]);
        out[h] = fmaxf((t[h] - lo) / (hi - lo + EPSV), 0.f);
    }
    if (L == 1) {
        __half2 p[4];
#pragma unroll
        for (int h = 0; h < 4; h++) p[h] = __floats2half2_rn(out[2 * h], out[2 * h + 1]);
        *(uint4*)&g_d2[(node * Bb + b) * 8] = *(uint4*)p;
    } else {
        float4* q = (float4*)&g_d3[(node * Bb + b) * 8];
        q[0] = make_float4(out[0], out[1], out[2], out[3]);
        q[1] = make_float4(out[4], out[5], out[6], out[7]);
    }
}

// ---- K7: final dot ----
__global__ void k_out(const float* __restrict__ Wout, const float* __restrict__ bout,
                      float* __restrict__ out) {
    int b = blockIdx.x;
    float p = 0.f;
    for (int idx = threadIdx.x; idx < M2 * 8; idx += blockDim.x) {
        p += g_d3[((idx >> 3) * Bb + b) * 8 + (idx & 7)] * Wout[idx];
    }
    __shared__ float sh[128];
    sh[threadIdx.x] = p;
    __syncthreads();
    for (int s = 64; s; s >>= 1) {
        if (threadIdx.x < (unsigned)s) sh[threadIdx.x] += sh[threadIdx.x + s];
        __syncthreads();
    }
    if (threadIdx.x == 0) out[b] = sh[0] + bout[0];
}

extern "C" void kernel_launch(void* const* d_in, const int* in_sizes, int n_in,
                              void* d_out, int out_size) {
    const float* x    = (const float*)d_in[0];
    const int*   e0s  = (const int*)d_in[1];
    const int*   e0d  = (const int*)d_in[2];
    const int*   e1s  = (const int*)d_in[3];
    const int*   e1d  = (const int*)d_in[4];
    const int*   e2s  = (const int*)d_in[5];
    const int*   e2d  = (const int*)d_in[6];
    const float* W0   = (const float*)d_in[7];
    const float* W1   = (const float*)d_in[8];
    const float* W2   = (const float*)d_in[9];
    const float* Wout = (const float*)d_in[10];
    const float* bout = (const float*)d_in[11];
    float* out = (float*)d_out;

    k_pre<<<TB + EB, 256>>>(x, e0d, e1d, e2d);
    k_scan<<<3, 1024>>>();
    k_fill<<<EB, 256>>>(e0s, e0d, e1s, e1d, e2s, e2d);
    k_agg0<<<M0 / 4, 256>>>(W0);
    k_aggL<<<M1 / 2, 128>>>(W1, 1);
    k_aggL<<<M2 / 2, 128>>>(W2, 2);
    k_out<<<Bb, 128>>>(Wout, bout, out);
}